// round 5
// baseline (speedup 1.0000x reference)
#include <cuda_runtime.h>
#include <cstddef>

// Problem constants (fixed by the dataset)
#define TBL 32      // T
#define DIM 64      // D

// One warp per bag, persistent grid-stride over bags. Lane l accumulates
// output elements [2l, 2l+1] (float2); a row (64 floats = 256B) is exactly
// one warp-wide float2 read (2 sectors per half, fully coalesced).
//
// Bag schedule is table-grouped: logical warp-index g maps to
//   table = g / (num_bags/32), group = g % (num_bags/32),
//   bag = group*32 + table
// so bags sharing table slice W[:, t, :] run temporally adjacent and
// repeated indices hit in L2. Grid-stride keeps all warps sweeping g-space
// in sync, preserving the ~9-table concurrent window (<L2 capacity), and
// eliminates the partial-wave tail of the one-bag-per-warp launch.
__global__ void __launch_bounds__(256, 8)
embbag_kernel(const float* __restrict__ W,
              const int*   __restrict__ feat,
              const int*   __restrict__ off,
              float*       __restrict__ out,
              int num_bags)
{
    const int lane        = threadIdx.x & 31;
    const int warp_global = (blockIdx.x * blockDim.x + threadIdx.x) >> 5;
    const int total_warps = (gridDim.x * blockDim.x) >> 5;
    const int grp         = num_bags >> 5;   // bags per table value

    for (int g = warp_global; g < num_bags; g += total_warps) {
        const int table = g / grp;
        const int group = g - table * grp;
        const int bag   = (group << 5) + table;   // bag % 32 == table

        const int start = off[bag];
        const int end   = off[bag + 1];

        float ax = 0.f, ay = 0.f;

        int j = start;
        // Unroll x4: four independent row-gathers in flight per lane.
        for (; j + 4 <= end; j += 4) {
            int e0 = __ldg(feat + j + 0);
            int e1 = __ldg(feat + j + 1);
            int e2 = __ldg(feat + j + 2);
            int e3 = __ldg(feat + j + 3);
            const float2* r0 = (const float2*)(W + ((size_t)e0 * TBL + table) * DIM);
            const float2* r1 = (const float2*)(W + ((size_t)e1 * TBL + table) * DIM);
            const float2* r2 = (const float2*)(W + ((size_t)e2 * TBL + table) * DIM);
            const float2* r3 = (const float2*)(W + ((size_t)e3 * TBL + table) * DIM);
            float2 v0 = __ldg(r0 + lane);
            float2 v1 = __ldg(r1 + lane);
            float2 v2 = __ldg(r2 + lane);
            float2 v3 = __ldg(r3 + lane);
            ax += v0.x + v1.x + v2.x + v3.x;
            ay += v0.y + v1.y + v2.y + v3.y;
        }
        for (; j < end; ++j) {
            int e = __ldg(feat + j);
            const float2* r = (const float2*)(W + ((size_t)e * TBL + table) * DIM);
            float2 v = __ldg(r + lane);
            ax += v.x;
            ay += v.y;
        }

        // Streaming store: keep the 8MB output from evicting hot table rows.
        float2* o = (float2*)(out + (size_t)bag * DIM);
        __stcs(o + lane, make_float2(ax, ay));
    }
}

extern "C" void kernel_launch(void* const* d_in, const int* in_sizes, int n_in,
                              void* d_out, int out_size)
{
    const float* W    = (const float*)d_in[0];   // (E, T, D) fp32
    const int*   feat = (const int*)d_in[1];     // (B*T*L,) int32
    const int*   off  = (const int*)d_in[2];     // (B*T+1,) int32

    int num_bags = in_sizes[2] - 1;              // B*T = 32768
    float* out = (float*)d_out;                  // (B, T, D) fp32

    // Persistent grid: exactly fill the chip (GB300: 152 SMs x 8 blocks of
    // 256 threads at occ 8). Cap by work so small inputs still behave.
    int threads = 256;                           // 8 warps per block
    int blocks = 152 * 8;                        // 1216 = one full wave
    int max_blocks = (num_bags * 32 + threads - 1) / threads;
    if (blocks > max_blocks) blocks = max_blocks;

    embbag_kernel<<<blocks, threads>>>(W, feat, off, out, num_bags);
}

// round 6
// speedup vs baseline: 1.0575x; 1.0575x over previous
#include <cuda_runtime.h>
#include <cstddef>

// Problem constants (fixed by the dataset)
#define TBL 32      // T
#define DIM 64      // D
#define GRP 1024    // bags per table value = num_bags / TBL

// One warp per bag. Lane l accumulates output elements [2l, 2l+1] (float2);
// a row (64 floats = 256B) is one warp-wide float2 read, fully coalesced.
// Bags are table-grouped so bags sharing table slice W[:, t, :] run
// temporally adjacent and repeated indices become L2 hits.
// Unroll x8: eight independent row-gathers in flight per lane to cover
// DRAM latency (we are MLP-bound, not bandwidth-bound).
__global__ void __launch_bounds__(256, 6)
embbag_kernel(const float* __restrict__ W,
              const int*   __restrict__ feat,
              const int*   __restrict__ off,
              float*       __restrict__ out,
              int num_bags)
{
    int gwarp = (blockIdx.x * blockDim.x + threadIdx.x) >> 5;
    int lane  = threadIdx.x & 31;
    if (gwarp >= num_bags) return;

    // Table-grouped schedule: warps [t*GRP, (t+1)*GRP) handle table t.
    const int table = gwarp >> 10;           // g / 1024
    const int group = gwarp & (GRP - 1);     // g % 1024
    const int bag   = (group << 5) + table;  // original bag id; bag % 32 == table

    const int start = off[bag];
    const int end   = off[bag + 1];

    const float2* Wl = (const float2*)W + lane;   // lane-offset base, float2 units

    float ax = 0.f, ay = 0.f;

    int j = start;
    // Unroll x8: eight independent gathers in flight per lane.
    for (; j + 8 <= end; j += 8) {
        int e0 = __ldg(feat + j + 0);
        int e1 = __ldg(feat + j + 1);
        int e2 = __ldg(feat + j + 2);
        int e3 = __ldg(feat + j + 3);
        int e4 = __ldg(feat + j + 4);
        int e5 = __ldg(feat + j + 5);
        int e6 = __ldg(feat + j + 6);
        int e7 = __ldg(feat + j + 7);
        float2 v0 = __ldg(Wl + ((size_t)e0 * TBL + table) * (DIM / 2));
        float2 v1 = __ldg(Wl + ((size_t)e1 * TBL + table) * (DIM / 2));
        float2 v2 = __ldg(Wl + ((size_t)e2 * TBL + table) * (DIM / 2));
        float2 v3 = __ldg(Wl + ((size_t)e3 * TBL + table) * (DIM / 2));
        float2 v4 = __ldg(Wl + ((size_t)e4 * TBL + table) * (DIM / 2));
        float2 v5 = __ldg(Wl + ((size_t)e5 * TBL + table) * (DIM / 2));
        float2 v6 = __ldg(Wl + ((size_t)e6 * TBL + table) * (DIM / 2));
        float2 v7 = __ldg(Wl + ((size_t)e7 * TBL + table) * (DIM / 2));
        ax += ((v0.x + v1.x) + (v2.x + v3.x)) + ((v4.x + v5.x) + (v6.x + v7.x));
        ay += ((v0.y + v1.y) + (v2.y + v3.y)) + ((v4.y + v5.y) + (v6.y + v7.y));
    }
    for (; j < end; ++j) {
        int e = __ldg(feat + j);
        float2 v = __ldg(Wl + ((size_t)e * TBL + table) * (DIM / 2));
        ax += v.x;
        ay += v.y;
    }

    // Streaming store: keep the 8MB output from evicting hot table rows.
    float2* o = (float2*)(out + (size_t)bag * DIM);
    __stcs(o + lane, make_float2(ax, ay));
}

extern "C" void kernel_launch(void* const* d_in, const int* in_sizes, int n_in,
                              void* d_out, int out_size)
{
    const float* W    = (const float*)d_in[0];   // (E, T, D) fp32
    const int*   feat = (const int*)d_in[1];     // (B*T*L,) int32
    const int*   off  = (const int*)d_in[2];     // (B*T+1,) int32

    int num_bags = in_sizes[2] - 1;              // B*T = 32768
    float* out = (float*)d_out;                  // (B, T, D) fp32

    int threads = 256;                           // 8 warps = 8 bags per block
    int total_threads = num_bags * 32;
    int blocks = (total_threads + threads - 1) / threads;

    embbag_kernel<<<blocks, threads>>>(W, feat, off, out, num_bags);
}

// round 7
// speedup vs baseline: 1.0650x; 1.0071x over previous
#include <cuda_runtime.h>
#include <cstddef>

// Problem constants (fixed by the dataset)
#define TBL 32      // T
#define DIM 64      // D
#define GRP 1024    // bags per table value = num_bags / TBL

// One warp per bag, float4 layout: 16 lanes cover one 256B row (lane reads
// float4 at dim offset (lane&15)*4). The two half-warps fetch DIFFERENT rows
// in the same LDG.128 instruction -> 2 independent rows per issue slot,
// 10 rows in flight per warp from 5 LDG slots. L=50 = 5 iters exactly.
// Bags are table-grouped so bags sharing table slice W[:, t, :] run
// temporally adjacent and repeated indices become L2 hits.
// End: halves combined with 4x shfl.xor(16), half-warp streaming store.
__global__ void __launch_bounds__(256, 6)
embbag_kernel(const float* __restrict__ W,
              const int*   __restrict__ feat,
              const int*   __restrict__ off,
              float*       __restrict__ out,
              int num_bags)
{
    int gwarp = (blockIdx.x * blockDim.x + threadIdx.x) >> 5;
    int lane  = threadIdx.x & 31;
    if (gwarp >= num_bags) return;

    // Table-grouped schedule: warps [t*GRP, (t+1)*GRP) handle table t.
    const int table = gwarp >> 10;           // g / 1024
    const int group = gwarp & (GRP - 1);     // g % 1024
    const int bag   = (group << 5) + table;  // original bag id; bag % 32 == table

    const int start = off[bag];
    const int end   = off[bag + 1];

    const int half = lane >> 4;              // which row of the pair
    const int hl   = lane & 15;              // float4 slot within the row

    // Row r lives at W + (r*TBL + table)*DIM floats = float4 index (e*32+table)*16.
    const float4* Wq = (const float4*)W + (size_t)table * (DIM / 4) + hl;
    // Now row e is at Wq + e * (TBL*DIM/4) = Wq + e*512.

    float4 acc = make_float4(0.f, 0.f, 0.f, 0.f);

    int j = start;
    // Main loop: 10 rows per iteration (5 LDG.128, each covering 2 rows).
    for (; j + 10 <= end; j += 10) {
        int e0 = __ldcs(feat + j + 0 + half);
        int e1 = __ldcs(feat + j + 2 + half);
        int e2 = __ldcs(feat + j + 4 + half);
        int e3 = __ldcs(feat + j + 6 + half);
        int e4 = __ldcs(feat + j + 8 + half);
        float4 v0 = __ldg(Wq + (size_t)e0 * (TBL * DIM / 4));
        float4 v1 = __ldg(Wq + (size_t)e1 * (TBL * DIM / 4));
        float4 v2 = __ldg(Wq + (size_t)e2 * (TBL * DIM / 4));
        float4 v3 = __ldg(Wq + (size_t)e3 * (TBL * DIM / 4));
        float4 v4 = __ldg(Wq + (size_t)e4 * (TBL * DIM / 4));
        acc.x += ((v0.x + v1.x) + (v2.x + v3.x)) + v4.x;
        acc.y += ((v0.y + v1.y) + (v2.y + v3.y)) + v4.y;
        acc.z += ((v0.z + v1.z) + (v2.z + v3.z)) + v4.z;
        acc.w += ((v0.w + v1.w) + (v2.w + v3.w)) + v4.w;
    }
    // Pair tail
    for (; j + 2 <= end; j += 2) {
        int e = __ldcs(feat + j + half);
        float4 v = __ldg(Wq + (size_t)e * (TBL * DIM / 4));
        acc.x += v.x; acc.y += v.y; acc.z += v.z; acc.w += v.w;
    }
    // Single-row tail (only half 0 contributes)
    if (j < end) {
        int e = __ldcs(feat + j);
        if (half == 0) {
            float4 v = __ldg(Wq + (size_t)e * (TBL * DIM / 4));
            acc.x += v.x; acc.y += v.y; acc.z += v.z; acc.w += v.w;
        }
    }

    // Combine the two half-warp partial sums (same dims, different rows).
    acc.x += __shfl_xor_sync(0xFFFFFFFFu, acc.x, 16);
    acc.y += __shfl_xor_sync(0xFFFFFFFFu, acc.y, 16);
    acc.z += __shfl_xor_sync(0xFFFFFFFFu, acc.z, 16);
    acc.w += __shfl_xor_sync(0xFFFFFFFFu, acc.w, 16);

    // Half-warp streaming store: 16 lanes x float4 = 256B row, coalesced.
    if (half == 0) {
        float4* o = (float4*)(out + (size_t)bag * DIM) + hl;
        __stcs(o, acc);
    }
}

extern "C" void kernel_launch(void* const* d_in, const int* in_sizes, int n_in,
                              void* d_out, int out_size)
{
    const float* W    = (const float*)d_in[0];   // (E, T, D) fp32
    const int*   feat = (const int*)d_in[1];     // (B*T*L,) int32
    const int*   off  = (const int*)d_in[2];     // (B*T+1,) int32

    int num_bags = in_sizes[2] - 1;              // B*T = 32768
    float* out = (float*)d_out;                  // (B, T, D) fp32

    int threads = 256;                           // 8 warps = 8 bags per block
    int total_threads = num_bags * 32;
    int blocks = (total_threads + threads - 1) / threads;

    embbag_kernel<<<blocks, threads>>>(W, feat, off, out, num_bags);
}